// round 6
// baseline (speedup 1.0000x reference)
#include <cuda_runtime.h>
#include <math.h>

// ---------------------------------------------------------------------------
// Problem constants (fixed shapes per reference: N=50000, D=256, H=8, E=800000)
// ---------------------------------------------------------------------------
#define NMAX  50000
#define EMAX  800000
#define ENMAX (EMAX + NMAX)   // edges incl. self loops
#define DDIM  256
#define HEADS 8
#define HD    32

// ---------------------------------------------------------------------------
// Scratch (device globals -- no allocation allowed)
// ---------------------------------------------------------------------------
__device__ float g_xp [NMAX * DDIM];   // x @ W
__device__ float g_agg[NMAX * DDIM];   // aggregated messages
__device__ float g_hn [NMAX * DDIM];   // layernorm output
__device__ float g_t1 [NMAX * DDIM];   // relu(hn@W1+b1)
__device__ float g_asrc[NMAX * HEADS];
__device__ float g_adst[NMAX * HEADS];
__device__ float g_m   [NMAX * HEADS];
__device__ float g_den [NMAX * HEADS];
__device__ float g_ex  [ENMAX * HEADS];
__device__ int   g_is64;               // 1 if edge_index is int64, 0 if int32

// ---------------------------------------------------------------------------
// Helpers
// ---------------------------------------------------------------------------
__device__ __forceinline__ void atomicMaxF(float* addr, float v) {
    // signed-int max for v>=0, unsigned min for v<0; init value must be -inf
    if (v >= 0.0f) atomicMax((int*)addr, __float_as_int(v));
    else           atomicMin((unsigned int*)addr, __float_as_uint(v));
}

// Load edge endpoints, robust to int32 vs int64 edge_index storage.
__device__ __forceinline__ void load_edge(const void* ei, int E, int edge,
                                          int& src, int& dst) {
    if (g_is64) {
        const long long* p = (const long long*)ei;
        src = (int)p[edge];
        dst = (int)p[E + edge];
    } else {
        const int* p = (const int*)ei;
        src = p[edge];
        dst = p[E + edge];
    }
}

// ---------------------------------------------------------------------------
// Dtype detection: if buffer is int64 (little-endian, values < 2^31), every
// odd 32-bit word of the first pairs is 0. For genuine int32 data the odd
// words are random node indices -> virtually impossible to all be 0.
// ---------------------------------------------------------------------------
__global__ void detect_dtype_kernel(const int* ei32, int E) {
    if (threadIdx.x == 0 && blockIdx.x == 0) {
        int cnt = (E < 128) ? E : 128;
        int is64 = 1;
        for (int i = 0; i < cnt; i++) {
            if (ei32[2 * i + 1] != 0) { is64 = 0; break; }
        }
        g_is64 = is64;
    }
}

// ---------------------------------------------------------------------------
// Init: agg=0, m=-inf, den=0
// ---------------------------------------------------------------------------
__global__ void init_kernel(int n) {
    int idx = blockIdx.x * blockDim.x + threadIdx.x;
    if (idx < n * DDIM) g_agg[idx] = 0.0f;
    if (idx < n * HEADS) {
        g_m[idx]   = __int_as_float(0xff800000);  // -inf
        g_den[idx] = 0.0f;
    }
}

// ---------------------------------------------------------------------------
// GEMM body: C[M,256] = A[M,256] @ B[256,256] (+bias) (optional relu)
// 128x128 tile, BK=16, 256 threads, 8x8 micro-tile
// ---------------------------------------------------------------------------
__device__ __forceinline__ void gemm256_body(
    const float* __restrict__ A, const float* __restrict__ B,
    const float* __restrict__ bias, float* __restrict__ C,
    int M, int relu)
{
    __shared__ float As[16][128 + 4];
    __shared__ float Bs[16][128];

    const int tid = threadIdx.x;
    const int tx = tid & 15;        // 0..15 -> col group of 8
    const int ty = tid >> 4;        // 0..15 -> row group of 8
    const int row0 = blockIdx.y * 128;
    const int col0 = blockIdx.x * 128;

    // A-tile load mapping: 128 rows x 16 cols -> 2 float4 / thread
    const int arow  = tid >> 1;         // 0..127
    const int acol4 = (tid & 1) * 2;    // float4 index 0 or 2 (of 4)
    // B-tile load mapping: 16 rows x 128 cols -> 2 float4 / thread
    const int brow  = tid >> 4;         // 0..15
    const int bcol4 = (tid & 15) * 2;   // float4 index 0..30

    float acc[8][8];
    #pragma unroll
    for (int i = 0; i < 8; i++)
        #pragma unroll
        for (int j = 0; j < 8; j++) acc[i][j] = 0.0f;

    for (int k0 = 0; k0 < DDIM; k0 += 16) {
        float4 a0 = make_float4(0.f, 0.f, 0.f, 0.f);
        float4 a1 = make_float4(0.f, 0.f, 0.f, 0.f);
        const int gr = row0 + arow;
        if (gr < M) {
            a0 = *reinterpret_cast<const float4*>(&A[gr * DDIM + k0 + acol4 * 4]);
            a1 = *reinterpret_cast<const float4*>(&A[gr * DDIM + k0 + acol4 * 4 + 4]);
        }
        float4 b0 = *reinterpret_cast<const float4*>(&B[(k0 + brow) * DDIM + col0 + bcol4 * 4]);
        float4 b1 = *reinterpret_cast<const float4*>(&B[(k0 + brow) * DDIM + col0 + bcol4 * 4 + 4]);

        __syncthreads();
        As[acol4 * 4 + 0][arow] = a0.x;
        As[acol4 * 4 + 1][arow] = a0.y;
        As[acol4 * 4 + 2][arow] = a0.z;
        As[acol4 * 4 + 3][arow] = a0.w;
        As[acol4 * 4 + 4][arow] = a1.x;
        As[acol4 * 4 + 5][arow] = a1.y;
        As[acol4 * 4 + 6][arow] = a1.z;
        As[acol4 * 4 + 7][arow] = a1.w;
        *reinterpret_cast<float4*>(&Bs[brow][bcol4 * 4])     = b0;
        *reinterpret_cast<float4*>(&Bs[brow][bcol4 * 4 + 4]) = b1;
        __syncthreads();

        #pragma unroll
        for (int k = 0; k < 16; k++) {
            float a[8], b[8];
            *reinterpret_cast<float4*>(&a[0]) = *reinterpret_cast<float4*>(&As[k][ty * 8]);
            *reinterpret_cast<float4*>(&a[4]) = *reinterpret_cast<float4*>(&As[k][ty * 8 + 4]);
            *reinterpret_cast<float4*>(&b[0]) = *reinterpret_cast<float4*>(&Bs[k][tx * 8]);
            *reinterpret_cast<float4*>(&b[4]) = *reinterpret_cast<float4*>(&Bs[k][tx * 8 + 4]);
            #pragma unroll
            for (int i = 0; i < 8; i++)
                #pragma unroll
                for (int j = 0; j < 8; j++)
                    acc[i][j] += a[i] * b[j];
        }
    }

    #pragma unroll
    for (int i = 0; i < 8; i++) {
        const int r = row0 + ty * 8 + i;
        if (r < M) {
            #pragma unroll
            for (int j = 0; j < 8; j++) {
                const int c = col0 + tx * 8 + j;
                float v = acc[i][j];
                if (bias) v += bias[c];
                if (relu) v = fmaxf(v, 0.0f);
                C[r * DDIM + c] = v;
            }
        }
    }
}

// Wrappers referencing device-global scratch directly (no symbol-address API).
__global__ __launch_bounds__(256) void gemm_xW_kernel(
    const float* __restrict__ x, const float* __restrict__ W, int M)
{
    gemm256_body(x, W, nullptr, g_xp, M, 0);
}

__global__ __launch_bounds__(256) void gemm_ffn1_kernel(
    const float* __restrict__ W1, const float* __restrict__ b1, int M)
{
    gemm256_body(g_hn, W1, b1, g_t1, M, 1);
}

__global__ __launch_bounds__(256) void gemm_ffn2_kernel(
    const float* __restrict__ W2, const float* __restrict__ b2,
    float* __restrict__ out, int M)
{
    gemm256_body(g_t1, W2, b2, out, M, 0);
}

// ---------------------------------------------------------------------------
// Per-node attention scores: a_src[n,h] = dot(xp[n,h,:], att_src[h,:])
// one block (256 thr) per node, one warp per head
// ---------------------------------------------------------------------------
__global__ void attn_scores_kernel(const float* __restrict__ att_src,
                                   const float* __restrict__ att_dst)
{
    const int n = blockIdx.x;
    const int tid = threadIdx.x;
    float v = g_xp[n * DDIM + tid];
    float s = v * att_src[tid];
    float d = v * att_dst[tid];
    #pragma unroll
    for (int o = 16; o > 0; o >>= 1) {
        s += __shfl_down_sync(0xffffffffu, s, o);
        d += __shfl_down_sync(0xffffffffu, d, o);
    }
    if ((tid & 31) == 0) {
        g_asrc[n * HEADS + (tid >> 5)] = s;
        g_adst[n * HEADS + (tid >> 5)] = d;
    }
}

// ---------------------------------------------------------------------------
// Edge pass 1: segment max of leaky_relu(a_src[src]+a_dst[dst]) over dst
// ---------------------------------------------------------------------------
__global__ void edge_max_kernel(const void* __restrict__ ei, int E, int n)
{
    const int idx = blockIdx.x * blockDim.x + threadIdx.x;
    if (idx >= (E + n) * HEADS) return;
    const int edge = idx >> 3;
    const int h = idx & 7;
    int src, dst;
    if (edge < E) load_edge(ei, E, edge, src, dst);
    else          src = dst = edge - E;
    if ((unsigned)src >= (unsigned)n || (unsigned)dst >= (unsigned)n) return;
    float e = g_asrc[src * HEADS + h] + g_adst[dst * HEADS + h];
    e = (e > 0.0f) ? e : 0.2f * e;
    atomicMaxF(&g_m[dst * HEADS + h], e);
}

// ---------------------------------------------------------------------------
// Edge pass 2: ex = exp(e - m[dst]); denom[dst] += ex
// ---------------------------------------------------------------------------
__global__ void edge_expsum_kernel(const void* __restrict__ ei, int E, int n)
{
    const int idx = blockIdx.x * blockDim.x + threadIdx.x;
    if (idx >= (E + n) * HEADS) return;
    const int edge = idx >> 3;
    const int h = idx & 7;
    int src, dst;
    if (edge < E) load_edge(ei, E, edge, src, dst);
    else          src = dst = edge - E;
    if ((unsigned)src >= (unsigned)n || (unsigned)dst >= (unsigned)n) {
        g_ex[idx] = 0.0f;
        return;
    }
    float e = g_asrc[src * HEADS + h] + g_adst[dst * HEADS + h];
    e = (e > 0.0f) ? e : 0.2f * e;
    float ex = __expf(e - g_m[dst * HEADS + h]);
    g_ex[idx] = ex;
    atomicAdd(&g_den[dst * HEADS + h], ex);
}

// ---------------------------------------------------------------------------
// Edge pass 3: scatter agg[dst,:] += alpha * xp[src,:], one block per edge
// ---------------------------------------------------------------------------
__global__ void scatter_kernel(const void* __restrict__ ei, int E, int n)
{
    const int edge = blockIdx.x;
    const int tid = threadIdx.x;           // 0..255, head = tid>>5
    int src, dst;
    if (edge < E) load_edge(ei, E, edge, src, dst);
    else          src = dst = edge - E;
    if ((unsigned)src >= (unsigned)n || (unsigned)dst >= (unsigned)n) return;
    const int h = tid >> 5;
    const float alpha = g_ex[edge * HEADS + h] /
                        (g_den[dst * HEADS + h] + 1e-16f);
    const float v = alpha * g_xp[src * DDIM + tid];
    atomicAdd(&g_agg[dst * DDIM + tid], v);
}

// ---------------------------------------------------------------------------
// Residual + LayerNorm: hn = LN(agg + bias + x) * g + b
// one block (256 thr) per node
// ---------------------------------------------------------------------------
__global__ void layernorm_kernel(const float* __restrict__ x,
                                 const float* __restrict__ bias,
                                 const float* __restrict__ gamma,
                                 const float* __restrict__ beta)
{
    const int nIdx = blockIdx.x;
    const int tid = threadIdx.x;
    __shared__ float ws[8], ws2[8];

    float r = g_agg[nIdx * DDIM + tid] + bias[tid] + x[nIdx * DDIM + tid];
    float s = r, s2 = r * r;
    #pragma unroll
    for (int o = 16; o > 0; o >>= 1) {
        s  += __shfl_down_sync(0xffffffffu, s, o);
        s2 += __shfl_down_sync(0xffffffffu, s2, o);
    }
    if ((tid & 31) == 0) { ws[tid >> 5] = s; ws2[tid >> 5] = s2; }
    __syncthreads();
    if (tid == 0) {
        float a = 0.f, b = 0.f;
        #pragma unroll
        for (int i = 0; i < 8; i++) { a += ws[i]; b += ws2[i]; }
        ws[0] = a; ws2[0] = b;
    }
    __syncthreads();
    const float mean = ws[0] * (1.0f / DDIM);
    float var = ws2[0] * (1.0f / DDIM) - mean * mean;
    const float inv = rsqrtf(var + 1e-5f);
    g_hn[nIdx * DDIM + tid] = (r - mean) * inv * gamma[tid] + beta[tid];
}

// ---------------------------------------------------------------------------
// Launch
// ---------------------------------------------------------------------------
extern "C" void kernel_launch(void* const* d_in, const int* in_sizes, int n_in,
                              void* d_out, int out_size)
{
    const float* x        = (const float*)d_in[0];
    const void*  ei       = d_in[1];          // int32 or int64, detected on device
    // d_in[2] = edge_attr (unused)
    const float* W        = (const float*)d_in[3];
    const float* att_src  = (const float*)d_in[4];
    const float* att_dst  = (const float*)d_in[5];
    const float* bias     = (const float*)d_in[6];
    const float* ln_g     = (const float*)d_in[7];
    const float* ln_b     = (const float*)d_in[8];
    const float* W1       = (const float*)d_in[9];
    const float* b1       = (const float*)d_in[10];
    const float* W2       = (const float*)d_in[11];
    const float* b2       = (const float*)d_in[12];
    float*       out      = (float*)d_out;

    const int N = in_sizes[0] / DDIM;
    const int E = in_sizes[1] / 2;

    // 0. detect edge_index dtype (int32 vs int64)
    detect_dtype_kernel<<<1, 32>>>((const int*)ei, E);

    // 1. init accumulators
    init_kernel<<<(N * DDIM + 255) / 256, 256>>>(N);

    // 2. xp = x @ W
    {
        dim3 grid(DDIM / 128, (N + 127) / 128);
        gemm_xW_kernel<<<grid, 256>>>(x, W, N);
    }

    // 3. attention scores
    attn_scores_kernel<<<N, 256>>>(att_src, att_dst);

    // 4. segment max
    {
        int tot = (E + N) * HEADS;
        edge_max_kernel<<<(tot + 255) / 256, 256>>>(ei, E, N);
    }

    // 5. exp + segment sum
    {
        int tot = (E + N) * HEADS;
        edge_expsum_kernel<<<(tot + 255) / 256, 256>>>(ei, E, N);
    }

    // 6. weighted scatter
    scatter_kernel<<<E + N, 256>>>(ei, E, N);

    // 7. residual + layernorm
    layernorm_kernel<<<N, 256>>>(x, bias, ln_g, ln_b);

    // 8. FFN
    {
        dim3 grid(DDIM / 128, (N + 127) / 128);
        gemm_ffn1_kernel<<<grid, 256>>>(W1, b1, N);
        gemm_ffn2_kernel<<<grid, 256>>>(W2, b2, out, N);
    }
}

// round 8
// speedup vs baseline: 1.8285x; 1.8285x over previous
#include <cuda_runtime.h>
#include <math.h>

// ---------------------------------------------------------------------------
// Problem constants (fixed shapes per reference: N=50000, D=256, H=8, E=800000)
// ---------------------------------------------------------------------------
#define NMAX  50016
#define EMAX  800000
#define ENMAX (EMAX + NMAX)   // edges incl. self loops
#define DDIM  256
#define HEADS 8
#define HD    32
#define NBCHUNKS 256          // max scan chunks (ceil(50000/256)=196 <= 256)

// ---------------------------------------------------------------------------
// Scratch (device globals -- no allocation allowed)
// ---------------------------------------------------------------------------
__device__ float g_xp [NMAX * DDIM];   // x @ W
__device__ float g_hn [NMAX * DDIM];   // layernorm output
__device__ float g_t1 [NMAX * DDIM];   // relu(hn@W1+b1)
__device__ float g_asrc[NMAX * HEADS];
__device__ float g_adst[NMAX * HEADS];
__device__ float g_m   [NMAX * HEADS];
__device__ float g_den [NMAX * HEADS];
__device__ float g_ex  [ENMAX * HEADS];  // pass1: leaky(e); pass2: exp(e-m)
__device__ int   g_src32[ENMAX];
__device__ int   g_dst32[ENMAX];
__device__ int   g_deg   [NMAX];
__device__ int   g_rowptr[NMAX + 1];
__device__ int   g_cursor[NMAX];
__device__ int   g_eid   [ENMAX];
__device__ int   g_part  [NBCHUNKS];
__device__ int   g_is64;               // 1 if edge_index is int64, 0 if int32

// ---------------------------------------------------------------------------
// Helpers
// ---------------------------------------------------------------------------
__device__ __forceinline__ void atomicMaxF(float* addr, float v) {
    if (v >= 0.0f) atomicMax((int*)addr, __float_as_int(v));
    else           atomicMin((unsigned int*)addr, __float_as_uint(v));
}

// ---------------------------------------------------------------------------
// Dtype detection: int64 little-endian with values < 2^31 -> odd words all 0.
// ---------------------------------------------------------------------------
__global__ void detect_dtype_kernel(const int* ei32, int E) {
    if (threadIdx.x == 0 && blockIdx.x == 0) {
        int cnt = (E < 128) ? E : 128;
        int is64 = 1;
        for (int i = 0; i < cnt; i++) {
            if (ei32[2 * i + 1] != 0) { is64 = 0; break; }
        }
        g_is64 = is64;
    }
}

// ---------------------------------------------------------------------------
// Init: deg=0, m=-inf, den=0
// ---------------------------------------------------------------------------
__global__ void init_kernel(int n) {
    int idx = blockIdx.x * blockDim.x + threadIdx.x;
    if (idx < n) g_deg[idx] = 0;
    if (idx < n * HEADS) {
        g_m[idx]   = __int_as_float(0xff800000);  // -inf
        g_den[idx] = 0.0f;
    }
}

// ---------------------------------------------------------------------------
// Convert edge indices to int32, count in-degree (self-loops appended E..E+N-1)
// ---------------------------------------------------------------------------
__global__ void deg_convert_kernel(const void* __restrict__ ei, int E, int n) {
    const int e = blockIdx.x * blockDim.x + threadIdx.x;
    const int total = E + n;
    if (e >= total) return;
    int src, dst;
    if (e < E) {
        if (g_is64) {
            const long long* p = (const long long*)ei;
            src = (int)p[e]; dst = (int)p[E + e];
        } else {
            const int* p = (const int*)ei;
            src = p[e]; dst = p[E + e];
        }
        if ((unsigned)src >= (unsigned)n) src = 0;
        if ((unsigned)dst >= (unsigned)n) dst = 0;
    } else {
        src = dst = e - E;
    }
    g_src32[e] = src;
    g_dst32[e] = dst;
    atomicAdd(&g_deg[dst], 1);
}

// ---------------------------------------------------------------------------
// Two-level exclusive scan of g_deg -> g_rowptr
// ---------------------------------------------------------------------------
__global__ void scan_chunk_kernel(int n) {          // grid = ceil(n/256), 256 thr
    __shared__ int s[256];
    const int tid = threadIdx.x;
    const int i = blockIdx.x * 256 + tid;
    int v = (i < n) ? g_deg[i] : 0;
    s[tid] = v;
    __syncthreads();
    #pragma unroll
    for (int o = 1; o < 256; o <<= 1) {
        int t = (tid >= o) ? s[tid - o] : 0;
        __syncthreads();
        s[tid] += t;
        __syncthreads();
    }
    if (i < n) g_rowptr[i] = s[tid] - v;            // exclusive within chunk
    if (tid == 255) g_part[blockIdx.x] = s[255];    // chunk total
}

__global__ void scan_part_kernel(int nb) {          // 1 block, 256 thr
    __shared__ int s[256];
    const int tid = threadIdx.x;
    int v = (tid < nb) ? g_part[tid] : 0;
    s[tid] = v;
    __syncthreads();
    #pragma unroll
    for (int o = 1; o < 256; o <<= 1) {
        int t = (tid >= o) ? s[tid - o] : 0;
        __syncthreads();
        s[tid] += t;
        __syncthreads();
    }
    if (tid < nb) g_part[tid] = s[tid] - v;         // exclusive chunk offsets
}

__global__ void scan_add_kernel(int n, int total) {
    const int i = blockIdx.x * 256 + threadIdx.x;
    if (i < n) {
        int r = g_rowptr[i] + g_part[blockIdx.x];
        g_rowptr[i] = r;
        g_cursor[i] = r;
    }
    if (i == 0) g_rowptr[n] = total;
}

__global__ void csr_fill_kernel(int total) {
    const int e = blockIdx.x * blockDim.x + threadIdx.x;
    if (e >= total) return;
    const int dst = g_dst32[e];
    const int pos = atomicAdd(&g_cursor[dst], 1);
    g_eid[pos] = e;
}

// ---------------------------------------------------------------------------
// GEMM body: C[M,256] = A[M,256] @ B[256,256] (+bias) (optional relu)
// 128x128 tile, BK=16, 256 threads, 8x8 micro-tile
// ---------------------------------------------------------------------------
__device__ __forceinline__ void gemm256_body(
    const float* __restrict__ A, const float* __restrict__ B,
    const float* __restrict__ bias, float* __restrict__ C,
    int M, int relu)
{
    __shared__ float As[16][128 + 4];
    __shared__ float Bs[16][128];

    const int tid = threadIdx.x;
    const int tx = tid & 15;
    const int ty = tid >> 4;
    const int row0 = blockIdx.y * 128;
    const int col0 = blockIdx.x * 128;

    const int arow  = tid >> 1;
    const int acol4 = (tid & 1) * 2;
    const int brow  = tid >> 4;
    const int bcol4 = (tid & 15) * 2;

    float acc[8][8];
    #pragma unroll
    for (int i = 0; i < 8; i++)
        #pragma unroll
        for (int j = 0; j < 8; j++) acc[i][j] = 0.0f;

    for (int k0 = 0; k0 < DDIM; k0 += 16) {
        float4 a0 = make_float4(0.f, 0.f, 0.f, 0.f);
        float4 a1 = make_float4(0.f, 0.f, 0.f, 0.f);
        const int gr = row0 + arow;
        if (gr < M) {
            a0 = *reinterpret_cast<const float4*>(&A[gr * DDIM + k0 + acol4 * 4]);
            a1 = *reinterpret_cast<const float4*>(&A[gr * DDIM + k0 + acol4 * 4 + 4]);
        }
        float4 b0 = *reinterpret_cast<const float4*>(&B[(k0 + brow) * DDIM + col0 + bcol4 * 4]);
        float4 b1 = *reinterpret_cast<const float4*>(&B[(k0 + brow) * DDIM + col0 + bcol4 * 4 + 4]);

        __syncthreads();
        As[acol4 * 4 + 0][arow] = a0.x;
        As[acol4 * 4 + 1][arow] = a0.y;
        As[acol4 * 4 + 2][arow] = a0.z;
        As[acol4 * 4 + 3][arow] = a0.w;
        As[acol4 * 4 + 4][arow] = a1.x;
        As[acol4 * 4 + 5][arow] = a1.y;
        As[acol4 * 4 + 6][arow] = a1.z;
        As[acol4 * 4 + 7][arow] = a1.w;
        *reinterpret_cast<float4*>(&Bs[brow][bcol4 * 4])     = b0;
        *reinterpret_cast<float4*>(&Bs[brow][bcol4 * 4 + 4]) = b1;
        __syncthreads();

        #pragma unroll
        for (int k = 0; k < 16; k++) {
            float a[8], b[8];
            *reinterpret_cast<float4*>(&a[0]) = *reinterpret_cast<float4*>(&As[k][ty * 8]);
            *reinterpret_cast<float4*>(&a[4]) = *reinterpret_cast<float4*>(&As[k][ty * 8 + 4]);
            *reinterpret_cast<float4*>(&b[0]) = *reinterpret_cast<float4*>(&Bs[k][tx * 8]);
            *reinterpret_cast<float4*>(&b[4]) = *reinterpret_cast<float4*>(&Bs[k][tx * 8 + 4]);
            #pragma unroll
            for (int i = 0; i < 8; i++)
                #pragma unroll
                for (int j = 0; j < 8; j++)
                    acc[i][j] += a[i] * b[j];
        }
    }

    #pragma unroll
    for (int i = 0; i < 8; i++) {
        const int r = row0 + ty * 8 + i;
        if (r < M) {
            #pragma unroll
            for (int j = 0; j < 8; j++) {
                const int c = col0 + tx * 8 + j;
                float v = acc[i][j];
                if (bias) v += bias[c];
                if (relu) v = fmaxf(v, 0.0f);
                C[r * DDIM + c] = v;
            }
        }
    }
}

__global__ __launch_bounds__(256) void gemm_xW_kernel(
    const float* __restrict__ x, const float* __restrict__ W, int M)
{
    gemm256_body(x, W, nullptr, g_xp, M, 0);
}

__global__ __launch_bounds__(256) void gemm_ffn1_kernel(
    const float* __restrict__ W1, const float* __restrict__ b1, int M)
{
    gemm256_body(g_hn, W1, b1, g_t1, M, 1);
}

__global__ __launch_bounds__(256) void gemm_ffn2_kernel(
    const float* __restrict__ W2, const float* __restrict__ b2,
    float* __restrict__ out, int M)
{
    gemm256_body(g_t1, W2, b2, out, M, 0);
}

// ---------------------------------------------------------------------------
// Per-node attention scores: a_src[n,h] = dot(xp[n,h,:], att_src[h,:])
// ---------------------------------------------------------------------------
__global__ void attn_scores_kernel(const float* __restrict__ att_src,
                                   const float* __restrict__ att_dst)
{
    const int n = blockIdx.x;
    const int tid = threadIdx.x;
    float v = g_xp[n * DDIM + tid];
    float s = v * att_src[tid];
    float d = v * att_dst[tid];
    #pragma unroll
    for (int o = 16; o > 0; o >>= 1) {
        s += __shfl_down_sync(0xffffffffu, s, o);
        d += __shfl_down_sync(0xffffffffu, d, o);
    }
    if ((tid & 31) == 0) {
        g_asrc[n * HEADS + (tid >> 5)] = s;
        g_adst[n * HEADS + (tid >> 5)] = d;
    }
}

// ---------------------------------------------------------------------------
// Edge pass 1: e = leaky_relu(a_src[src]+a_dst[dst]); store e; segment max
// ---------------------------------------------------------------------------
__global__ void edge_max_kernel(int total)
{
    const int idx = blockIdx.x * blockDim.x + threadIdx.x;
    if (idx >= total * HEADS) return;
    const int edge = idx >> 3;
    const int h = idx & 7;
    const int src = g_src32[edge];
    const int dst = g_dst32[edge];
    float e = g_asrc[src * HEADS + h] + g_adst[dst * HEADS + h];
    e = (e > 0.0f) ? e : 0.2f * e;
    g_ex[idx] = e;
    atomicMaxF(&g_m[dst * HEADS + h], e);
}

// ---------------------------------------------------------------------------
// Edge pass 2: ex = exp(e - m[dst]); denom[dst] += ex (reads stored e)
// ---------------------------------------------------------------------------
__global__ void edge_expsum_kernel(int total)
{
    const int idx = blockIdx.x * blockDim.x + threadIdx.x;
    if (idx >= total * HEADS) return;
    const int edge = idx >> 3;
    const int h = idx & 7;
    const int dst = g_dst32[edge];
    float ex = __expf(g_ex[idx] - g_m[dst * HEADS + h]);
    g_ex[idx] = ex;
    atomicAdd(&g_den[dst * HEADS + h], ex);
}

// ---------------------------------------------------------------------------
// Fused gather-aggregation + residual + LayerNorm. One block per dst node.
// acc[d] = sum over incoming edges of alpha(e,h) * xp[src, d]
// hn = LN(acc + bias + x) * gamma + beta
// ---------------------------------------------------------------------------
__global__ __launch_bounds__(256) void aggregate_ln_kernel(
    const float* __restrict__ x,
    const float* __restrict__ bias,
    const float* __restrict__ gamma,
    const float* __restrict__ beta)
{
    const int node = blockIdx.x;
    const int tid = threadIdx.x;
    const int h = tid >> 5;
    const int beg = g_rowptr[node];
    const int end = g_rowptr[node + 1];
    const float inv_den = 1.0f / (g_den[node * HEADS + h] + 1e-16f);

    float acc = 0.0f;
    int i = beg;
    for (; i + 4 <= end; i += 4) {
        const int e0 = g_eid[i],     e1 = g_eid[i + 1];
        const int e2 = g_eid[i + 2], e3 = g_eid[i + 3];
        const int s0 = g_src32[e0], s1 = g_src32[e1];
        const int s2 = g_src32[e2], s3 = g_src32[e3];
        const float a0 = g_ex[e0 * HEADS + h] * inv_den;
        const float a1 = g_ex[e1 * HEADS + h] * inv_den;
        const float a2 = g_ex[e2 * HEADS + h] * inv_den;
        const float a3 = g_ex[e3 * HEADS + h] * inv_den;
        const float v0 = g_xp[s0 * DDIM + tid];
        const float v1 = g_xp[s1 * DDIM + tid];
        const float v2 = g_xp[s2 * DDIM + tid];
        const float v3 = g_xp[s3 * DDIM + tid];
        acc += a0 * v0 + a1 * v1 + a2 * v2 + a3 * v3;
    }
    for (; i < end; i++) {
        const int e = g_eid[i];
        const int s = g_src32[e];
        acc += g_ex[e * HEADS + h] * inv_den * g_xp[s * DDIM + tid];
    }

    // residual + LayerNorm
    __shared__ float ws[8], ws2[8];
    float r = acc + bias[tid] + x[node * DDIM + tid];
    float sm = r, s2 = r * r;
    #pragma unroll
    for (int o = 16; o > 0; o >>= 1) {
        sm += __shfl_down_sync(0xffffffffu, sm, o);
        s2 += __shfl_down_sync(0xffffffffu, s2, o);
    }
    if ((tid & 31) == 0) { ws[tid >> 5] = sm; ws2[tid >> 5] = s2; }
    __syncthreads();
    if (tid == 0) {
        float a = 0.f, b = 0.f;
        #pragma unroll
        for (int k = 0; k < 8; k++) { a += ws[k]; b += ws2[k]; }
        ws[0] = a; ws2[0] = b;
    }
    __syncthreads();
    const float mean = ws[0] * (1.0f / DDIM);
    const float var = ws2[0] * (1.0f / DDIM) - mean * mean;
    const float inv = rsqrtf(var + 1e-5f);
    g_hn[node * DDIM + tid] = (r - mean) * inv * gamma[tid] + beta[tid];
}

// ---------------------------------------------------------------------------
// Launch
// ---------------------------------------------------------------------------
extern "C" void kernel_launch(void* const* d_in, const int* in_sizes, int n_in,
                              void* d_out, int out_size)
{
    const float* x        = (const float*)d_in[0];
    const void*  ei       = d_in[1];
    // d_in[2] = edge_attr (unused)
    const float* W        = (const float*)d_in[3];
    const float* att_src  = (const float*)d_in[4];
    const float* att_dst  = (const float*)d_in[5];
    const float* bias     = (const float*)d_in[6];
    const float* ln_g     = (const float*)d_in[7];
    const float* ln_b     = (const float*)d_in[8];
    const float* W1       = (const float*)d_in[9];
    const float* b1       = (const float*)d_in[10];
    const float* W2       = (const float*)d_in[11];
    const float* b2       = (const float*)d_in[12];
    float*       out      = (float*)d_out;

    const int N = in_sizes[0] / DDIM;
    const int E = in_sizes[1] / 2;
    const int total = E + N;
    const int nchunks = (N + 255) / 256;

    // 0. detect dtype, init accumulators
    detect_dtype_kernel<<<1, 32>>>((const int*)ei, E);
    init_kernel<<<(N * HEADS + 255) / 256, 256>>>(N);

    // 1. convert indices + degree count
    deg_convert_kernel<<<(total + 255) / 256, 256>>>(ei, E, N);

    // 2. CSR build (exclusive scan + fill)
    scan_chunk_kernel<<<nchunks, 256>>>(N);
    scan_part_kernel<<<1, 256>>>(nchunks);
    scan_add_kernel<<<nchunks, 256>>>(N, total);
    csr_fill_kernel<<<(total + 255) / 256, 256>>>(total);

    // 3. xp = x @ W
    {
        dim3 grid(DDIM / 128, (N + 127) / 128);
        gemm_xW_kernel<<<grid, 256>>>(x, W, N);
    }

    // 4. attention scores
    attn_scores_kernel<<<N, 256>>>(att_src, att_dst);

    // 5. segment max (stores leaky e)
    edge_max_kernel<<<(total * HEADS + 255) / 256, 256>>>(total);

    // 6. exp + segment sum
    edge_expsum_kernel<<<(total * HEADS + 255) / 256, 256>>>(total);

    // 7. gather-aggregate + residual + layernorm (fused)
    aggregate_ln_kernel<<<N, 256>>>(x, bias, ln_g, ln_b);

    // 8. FFN
    {
        dim3 grid(DDIM / 128, (N + 127) / 128);
        gemm_ffn1_kernel<<<grid, 256>>>(W1, b1, N);
        gemm_ffn2_kernel<<<grid, 256>>>(W2, b2, out, N);
    }
}

// round 12
// speedup vs baseline: 2.2855x; 1.2499x over previous
#include <cuda_runtime.h>
#include <cuda_bf16.h>
#include <math.h>
#include <stdint.h>

// ---------------------------------------------------------------------------
// Problem constants (fixed shapes per reference: N=50000, D=256, H=8, E=800000)
// ---------------------------------------------------------------------------
#define NMAX  50016
#define EMAX  800000
#define ENMAX (EMAX + NMAX)   // edges incl. self loops
#define DDIM  256
#define HEADS 8
#define HD    32
#define NBCHUNKS 256          // max scan chunks (ceil(50000/256)=196 <= 256)

// mma GEMM tiling
#define BK      32            // K per SMEM chunk
#define ASTRIDE 40            // bf16 elements per SMEM row (bank-conflict-free)

// ---------------------------------------------------------------------------
// Scratch (device globals -- no allocation allowed)
// ---------------------------------------------------------------------------
__device__ float g_xp [NMAX * DDIM];   // x @ W
__device__ float g_hn [NMAX * DDIM];   // layernorm output
__device__ float g_t1 [NMAX * DDIM];   // relu(hn@W1+b1)
__device__ float g_asrc[NMAX * HEADS];
__device__ float g_adst[NMAX * HEADS];
__device__ float g_m   [NMAX * HEADS];
__device__ float g_den [NMAX * HEADS];
__device__ float g_ex  [ENMAX * HEADS];  // pass1: leaky(e); pass2: exp(e-m)
__device__ int   g_src32[ENMAX];
__device__ int   g_dst32[ENMAX];
__device__ int   g_deg   [NMAX];
__device__ int   g_rowptr[NMAX + 1];
__device__ int   g_cursor[NMAX];
__device__ int   g_eid   [ENMAX];
__device__ int   g_part  [NBCHUNKS];
__device__ int   g_is64;               // 1 if edge_index is int64, 0 if int32

// ---------------------------------------------------------------------------
// Helpers
// ---------------------------------------------------------------------------
__device__ __forceinline__ void atomicMaxF(float* addr, float v) {
    if (v >= 0.0f) atomicMax((int*)addr, __float_as_int(v));
    else           atomicMin((unsigned int*)addr, __float_as_uint(v));
}

__device__ __forceinline__ uint32_t pack_bf(__nv_bfloat16 a, __nv_bfloat16 b) {
    __nv_bfloat162 t;
    t.x = a; t.y = b;
    return *reinterpret_cast<uint32_t*>(&t);
}

// mma.sync m16n8k16 bf16 -> f32, accumulate in place (sm_80+, arch-portable)
__device__ __forceinline__ void mma_bf16(float* c, const uint32_t* a, const uint32_t* b) {
    asm volatile(
        "mma.sync.aligned.m16n8k16.row.col.f32.bf16.bf16.f32 "
        "{%0,%1,%2,%3}, {%4,%5,%6,%7}, {%8,%9}, {%0,%1,%2,%3};\n"
        : "+f"(c[0]), "+f"(c[1]), "+f"(c[2]), "+f"(c[3])
        : "r"(a[0]), "r"(a[1]), "r"(a[2]), "r"(a[3]), "r"(b[0]), "r"(b[1]));
}

// ---------------------------------------------------------------------------
// Tensor GEMM via mma.sync: C[M,256] = A[M,256] @ B[256,256] (+bias)(relu)
// 3-term bf16 hi/lo split. CTA = 128x128 tile, 256 threads (8 warps, 4m x 2n).
// ---------------------------------------------------------------------------
__device__ void gemm_mma_body(const float* __restrict__ A, const float* __restrict__ B,
                              const float* __restrict__ bias, float* __restrict__ C,
                              int M, int relu)
{
    __shared__ __nv_bfloat16 Ah[128 * ASTRIDE];
    __shared__ __nv_bfloat16 Al[128 * ASTRIDE];
    __shared__ __nv_bfloat16 Bh[128 * ASTRIDE];
    __shared__ __nv_bfloat16 Bl[128 * ASTRIDE];

    const int tid  = threadIdx.x;
    const int wid  = tid >> 5;
    const int lane = tid & 31;
    const int wm   = wid & 3;       // 0..3 -> 32-row slice
    const int wn   = wid >> 2;      // 0..1 -> 64-col slice
    const int row0 = blockIdx.y * 128;
    const int col0 = blockIdx.x * 128;
    const int lr   = lane >> 2;     // 0..7
    const int lc   = lane & 3;      // 0..3

    float acc[2][8][4];
    #pragma unroll
    for (int mi = 0; mi < 2; mi++)
        #pragma unroll
        for (int ni = 0; ni < 8; ni++)
            #pragma unroll
            for (int q = 0; q < 4; q++) acc[mi][ni][q] = 0.0f;

    for (int kc = 0; kc < DDIM; kc += BK) {
        // ---- A chunk: 128 rows x 32 K fp32 -> hi/lo bf16 ----
        #pragma unroll
        for (int i = 0; i < 4; i++) {
            const int f4  = tid + i * 256;     // 1024 float4
            const int row = f4 >> 3;           // 8 f4 per row
            const int kq  = f4 & 7;            // 4 k each
            const int gr  = row0 + row;
            float4 v = make_float4(0.f, 0.f, 0.f, 0.f);
            if (gr < M) v = *reinterpret_cast<const float4*>(&A[gr * DDIM + kc + kq * 4]);
            __nv_bfloat16 hx = __float2bfloat16(v.x), hy = __float2bfloat16(v.y);
            __nv_bfloat16 hz = __float2bfloat16(v.z), hw = __float2bfloat16(v.w);
            __nv_bfloat16 lx = __float2bfloat16(v.x - __bfloat162float(hx));
            __nv_bfloat16 ly = __float2bfloat16(v.y - __bfloat162float(hy));
            __nv_bfloat16 lz = __float2bfloat16(v.z - __bfloat162float(hz));
            __nv_bfloat16 lw = __float2bfloat16(v.w - __bfloat162float(hw));
            const int o = row * ASTRIDE + kq * 4;
            *reinterpret_cast<uint32_t*>(&Ah[o])     = pack_bf(hx, hy);
            *reinterpret_cast<uint32_t*>(&Ah[o + 2]) = pack_bf(hz, hw);
            *reinterpret_cast<uint32_t*>(&Al[o])     = pack_bf(lx, ly);
            *reinterpret_cast<uint32_t*>(&Al[o + 2]) = pack_bf(lz, lw);
        }
        // ---- B chunk transposed: B[k][n] -> Bs[n][k] ----
        #pragma unroll
        for (int i = 0; i < 16; i++) {
            const int idx = tid + i * 256;     // 4096 elements
            const int k = idx >> 7;            // 0..31
            const int n = idx & 127;
            const float v = B[(kc + k) * DDIM + col0 + n];
            const __nv_bfloat16 h = __float2bfloat16(v);
            const __nv_bfloat16 l = __float2bfloat16(v - __bfloat162float(h));
            Bh[n * ASTRIDE + k] = h;
            Bl[n * ASTRIDE + k] = l;
        }
        __syncthreads();

        #pragma unroll
        for (int ks = 0; ks < 2; ks++) {       // two k16 steps
            const int pb = ks * 8;             // k-pair base (u32 pairs)
            // A fragments (hi and lo), 2 m-tiles
            uint32_t ah[2][4], al[2][4];
            #pragma unroll
            for (int mi = 0; mi < 2; mi++) {
                const int r  = wm * 32 + mi * 16 + lr;
                const int o0 = r * ASTRIDE + (pb + lc) * 2;
                const int o8 = (r + 8) * ASTRIDE + (pb + lc) * 2;
                ah[mi][0] = *reinterpret_cast<uint32_t*>(&Ah[o0]);
                ah[mi][1] = *reinterpret_cast<uint32_t*>(&Ah[o8]);
                ah[mi][2] = *reinterpret_cast<uint32_t*>(&Ah[o0 + 8]);
                ah[mi][3] = *reinterpret_cast<uint32_t*>(&Ah[o8 + 8]);
                al[mi][0] = *reinterpret_cast<uint32_t*>(&Al[o0]);
                al[mi][1] = *reinterpret_cast<uint32_t*>(&Al[o8]);
                al[mi][2] = *reinterpret_cast<uint32_t*>(&Al[o0 + 8]);
                al[mi][3] = *reinterpret_cast<uint32_t*>(&Al[o8 + 8]);
            }
            // B fragments (hi and lo), 8 n-tiles
            uint32_t bh[8][2], bl[8][2];
            #pragma unroll
            for (int ni = 0; ni < 8; ni++) {
                const int n = wn * 64 + ni * 8 + lr;
                const int o = n * ASTRIDE + (pb + lc) * 2;
                bh[ni][0] = *reinterpret_cast<uint32_t*>(&Bh[o]);
                bh[ni][1] = *reinterpret_cast<uint32_t*>(&Bh[o + 8]);
                bl[ni][0] = *reinterpret_cast<uint32_t*>(&Bl[o]);
                bl[ni][1] = *reinterpret_cast<uint32_t*>(&Bl[o + 8]);
            }
            // 3-term accumulation
            #pragma unroll
            for (int mi = 0; mi < 2; mi++)
                #pragma unroll
                for (int ni = 0; ni < 8; ni++) {
                    mma_bf16(acc[mi][ni], ah[mi], bh[ni]);
                    mma_bf16(acc[mi][ni], ah[mi], bl[ni]);
                    mma_bf16(acc[mi][ni], al[mi], bh[ni]);
                }
        }
        __syncthreads();
    }

    // ---- epilogue ----
    #pragma unroll
    for (int mi = 0; mi < 2; mi++) {
        #pragma unroll
        for (int half = 0; half < 2; half++) {
            const int r = row0 + wm * 32 + mi * 16 + lr + half * 8;
            if (r < M) {
                #pragma unroll
                for (int ni = 0; ni < 8; ni++) {
                    const int c = col0 + wn * 64 + ni * 8 + lc * 2;
                    float2 o;
                    o.x = acc[mi][ni][half * 2 + 0];
                    o.y = acc[mi][ni][half * 2 + 1];
                    if (bias) {
                        o.x += bias[c];
                        o.y += bias[c + 1];
                    }
                    if (relu) {
                        o.x = fmaxf(o.x, 0.f);
                        o.y = fmaxf(o.y, 0.f);
                    }
                    *reinterpret_cast<float2*>(&C[r * DDIM + c]) = o;
                }
            }
        }
    }
}

__global__ __launch_bounds__(256) void gemm_xW_kernel(
    const float* __restrict__ x, const float* __restrict__ W, int M)
{
    gemm_mma_body(x, W, nullptr, g_xp, M, 0);
}

__global__ __launch_bounds__(256) void gemm_ffn1_kernel(
    const float* __restrict__ W1, const float* __restrict__ b1, int M)
{
    gemm_mma_body(g_hn, W1, b1, g_t1, M, 1);
}

__global__ __launch_bounds__(256) void gemm_ffn2_kernel(
    const float* __restrict__ W2, const float* __restrict__ b2,
    float* __restrict__ out, int M)
{
    gemm_mma_body(g_t1, W2, b2, out, M, 0);
}

// ---------------------------------------------------------------------------
// Dtype detection: int64 little-endian with values < 2^31 -> odd words all 0.
// ---------------------------------------------------------------------------
__global__ void detect_dtype_kernel(const int* ei32, int E) {
    if (threadIdx.x == 0 && blockIdx.x == 0) {
        int cnt = (E < 128) ? E : 128;
        int is64 = 1;
        for (int i = 0; i < cnt; i++) {
            if (ei32[2 * i + 1] != 0) { is64 = 0; break; }
        }
        g_is64 = is64;
    }
}

// ---------------------------------------------------------------------------
// Init: deg=0, m=-inf, den=0
// ---------------------------------------------------------------------------
__global__ void init_kernel(int n) {
    int idx = blockIdx.x * blockDim.x + threadIdx.x;
    if (idx < n) g_deg[idx] = 0;
    if (idx < n * HEADS) {
        g_m[idx]   = __int_as_float(0xff800000);  // -inf
        g_den[idx] = 0.0f;
    }
}

// ---------------------------------------------------------------------------
// Convert edge indices to int32, count in-degree (self-loops appended E..E+N-1)
// ---------------------------------------------------------------------------
__global__ void deg_convert_kernel(const void* __restrict__ ei, int E, int n) {
    const int e = blockIdx.x * blockDim.x + threadIdx.x;
    const int total = E + n;
    if (e >= total) return;
    int src, dst;
    if (e < E) {
        if (g_is64) {
            const long long* p = (const long long*)ei;
            src = (int)p[e]; dst = (int)p[E + e];
        } else {
            const int* p = (const int*)ei;
            src = p[e]; dst = p[E + e];
        }
        if ((unsigned)src >= (unsigned)n) src = 0;
        if ((unsigned)dst >= (unsigned)n) dst = 0;
    } else {
        src = dst = e - E;
    }
    g_src32[e] = src;
    g_dst32[e] = dst;
    atomicAdd(&g_deg[dst], 1);
}

// ---------------------------------------------------------------------------
// Two-level exclusive scan of g_deg -> g_rowptr
// ---------------------------------------------------------------------------
__global__ void scan_chunk_kernel(int n) {
    __shared__ int s[256];
    const int tid = threadIdx.x;
    const int i = blockIdx.x * 256 + tid;
    int v = (i < n) ? g_deg[i] : 0;
    s[tid] = v;
    __syncthreads();
    #pragma unroll
    for (int o = 1; o < 256; o <<= 1) {
        int t = (tid >= o) ? s[tid - o] : 0;
        __syncthreads();
        s[tid] += t;
        __syncthreads();
    }
    if (i < n) g_rowptr[i] = s[tid] - v;
    if (tid == 255) g_part[blockIdx.x] = s[255];
}

__global__ void scan_part_kernel(int nb) {
    __shared__ int s[256];
    const int tid = threadIdx.x;
    int v = (tid < nb) ? g_part[tid] : 0;
    s[tid] = v;
    __syncthreads();
    #pragma unroll
    for (int o = 1; o < 256; o <<= 1) {
        int t = (tid >= o) ? s[tid - o] : 0;
        __syncthreads();
        s[tid] += t;
        __syncthreads();
    }
    if (tid < nb) g_part[tid] = s[tid] - v;
}

__global__ void scan_add_kernel(int n, int total) {
    const int i = blockIdx.x * 256 + threadIdx.x;
    if (i < n) {
        int r = g_rowptr[i] + g_part[blockIdx.x];
        g_rowptr[i] = r;
        g_cursor[i] = r;
    }
    if (i == 0) g_rowptr[n] = total;
}

__global__ void csr_fill_kernel(int total) {
    const int e = blockIdx.x * blockDim.x + threadIdx.x;
    if (e >= total) return;
    const int dst = g_dst32[e];
    const int pos = atomicAdd(&g_cursor[dst], 1);
    g_eid[pos] = e;
}

// ---------------------------------------------------------------------------
// Per-node attention scores: a_src[n,h] = dot(xp[n,h,:], att_src[h,:])
// ---------------------------------------------------------------------------
__global__ void attn_scores_kernel(const float* __restrict__ att_src,
                                   const float* __restrict__ att_dst)
{
    const int n = blockIdx.x;
    const int tid = threadIdx.x;
    float v = g_xp[n * DDIM + tid];
    float s = v * att_src[tid];
    float d = v * att_dst[tid];
    #pragma unroll
    for (int o = 16; o > 0; o >>= 1) {
        s += __shfl_down_sync(0xffffffffu, s, o);
        d += __shfl_down_sync(0xffffffffu, d, o);
    }
    if ((tid & 31) == 0) {
        g_asrc[n * HEADS + (tid >> 5)] = s;
        g_adst[n * HEADS + (tid >> 5)] = d;
    }
}

// ---------------------------------------------------------------------------
// Edge pass 1: e = leaky_relu(a_src[src]+a_dst[dst]); store e; segment max
// ---------------------------------------------------------------------------
__global__ void edge_max_kernel(int total)
{
    const int idx = blockIdx.x * blockDim.x + threadIdx.x;
    if (idx >= total * HEADS) return;
    const int edge = idx >> 3;
    const int h = idx & 7;
    const int src = g_src32[edge];
    const int dst = g_dst32[edge];
    float e = g_asrc[src * HEADS + h] + g_adst[dst * HEADS + h];
    e = (e > 0.0f) ? e : 0.2f * e;
    g_ex[idx] = e;
    atomicMaxF(&g_m[dst * HEADS + h], e);
}

// ---------------------------------------------------------------------------
// Edge pass 2: ex = exp(e - m[dst]); denom[dst] += ex (reads stored e)
// ---------------------------------------------------------------------------
__global__ void edge_expsum_kernel(int total)
{
    const int idx = blockIdx.x * blockDim.x + threadIdx.x;
    if (idx >= total * HEADS) return;
    const int edge = idx >> 3;
    const int h = idx & 7;
    const int dst = g_dst32[edge];
    float ex = __expf(g_ex[idx] - g_m[dst * HEADS + h]);
    g_ex[idx] = ex;
    atomicAdd(&g_den[dst * HEADS + h], ex);
}

// ---------------------------------------------------------------------------
// Fused gather-aggregation + residual + LayerNorm. One block per dst node.
// ---------------------------------------------------------------------------
__global__ __launch_bounds__(256) void aggregate_ln_kernel(
    const float* __restrict__ x,
    const float* __restrict__ bias,
    const float* __restrict__ gamma,
    const float* __restrict__ beta)
{
    const int node = blockIdx.x;
    const int tid = threadIdx.x;
    const int h = tid >> 5;
    const int beg = g_rowptr[node];
    const int end = g_rowptr[node + 1];
    const float inv_den = 1.0f / (g_den[node * HEADS + h] + 1e-16f);

    float acc = 0.0f;
    int i = beg;
    for (; i + 4 <= end; i += 4) {
        const int e0 = g_eid[i],     e1 = g_eid[i + 1];
        const int e2 = g_eid[i + 2], e3 = g_eid[i + 3];
        const int s0 = g_src32[e0], s1 = g_src32[e1];
        const int s2 = g_src32[e2], s3 = g_src32[e3];
        const float a0 = g_ex[e0 * HEADS + h] * inv_den;
        const float a1 = g_ex[e1 * HEADS + h] * inv_den;
        const float a2 = g_ex[e2 * HEADS + h] * inv_den;
        const float a3 = g_ex[e3 * HEADS + h] * inv_den;
        const float v0 = g_xp[s0 * DDIM + tid];
        const float v1 = g_xp[s1 * DDIM + tid];
        const float v2 = g_xp[s2 * DDIM + tid];
        const float v3 = g_xp[s3 * DDIM + tid];
        acc += a0 * v0 + a1 * v1 + a2 * v2 + a3 * v3;
    }
    for (; i < end; i++) {
        const int e = g_eid[i];
        const int s = g_src32[e];
        acc += g_ex[e * HEADS + h] * inv_den * g_xp[s * DDIM + tid];
    }

    __shared__ float ws[8], ws2[8];
    float r = acc + bias[tid] + x[node * DDIM + tid];
    float sm = r, s2 = r * r;
    #pragma unroll
    for (int o = 16; o > 0; o >>= 1) {
        sm += __shfl_down_sync(0xffffffffu, sm, o);
        s2 += __shfl_down_sync(0xffffffffu, s2, o);
    }
    if ((tid & 31) == 0) { ws[tid >> 5] = sm; ws2[tid >> 5] = s2; }
    __syncthreads();
    if (tid == 0) {
        float a = 0.f, b = 0.f;
        #pragma unroll
        for (int k = 0; k < 8; k++) { a += ws[k]; b += ws2[k]; }
        ws[0] = a; ws2[0] = b;
    }
    __syncthreads();
    const float mean = ws[0] * (1.0f / DDIM);
    const float var = ws2[0] * (1.0f / DDIM) - mean * mean;
    const float inv = rsqrtf(var + 1e-5f);
    g_hn[node * DDIM + tid] = (r - mean) * inv * gamma[tid] + beta[tid];
}

// ---------------------------------------------------------------------------
// Launch
// ---------------------------------------------------------------------------
extern "C" void kernel_launch(void* const* d_in, const int* in_sizes, int n_in,
                              void* d_out, int out_size)
{
    const float* x        = (const float*)d_in[0];
    const void*  ei       = d_in[1];
    // d_in[2] = edge_attr (unused)
    const float* W        = (const float*)d_in[3];
    const float* att_src  = (const float*)d_in[4];
    const float* att_dst  = (const float*)d_in[5];
    const float* bias     = (const float*)d_in[6];
    const float* ln_g     = (const float*)d_in[7];
    const float* ln_b     = (const float*)d_in[8];
    const float* W1       = (const float*)d_in[9];
    const float* b1       = (const float*)d_in[10];
    const float* W2       = (const float*)d_in[11];
    const float* b2       = (const float*)d_in[12];
    float*       out      = (float*)d_out;

    const int N = in_sizes[0] / DDIM;
    const int E = in_sizes[1] / 2;
    const int total = E + N;
    const int nchunks = (N + 255) / 256;
    const dim3 ggrid(DDIM / 128, (N + 127) / 128);

    // 0. detect dtype, init accumulators
    detect_dtype_kernel<<<1, 32>>>((const int*)ei, E);
    init_kernel<<<(N * HEADS + 255) / 256, 256>>>(N);

    // 1. convert indices + degree count
    deg_convert_kernel<<<(total + 255) / 256, 256>>>(ei, E, N);

    // 2. CSR build (exclusive scan + fill)
    scan_chunk_kernel<<<nchunks, 256>>>(N);
    scan_part_kernel<<<1, 256>>>(nchunks);
    scan_add_kernel<<<nchunks, 256>>>(N, total);
    csr_fill_kernel<<<(total + 255) / 256, 256>>>(total);

    // 3. xp = x @ W   (mma.sync tensor path)
    gemm_xW_kernel<<<ggrid, 256>>>(x, W, N);

    // 4. attention scores
    attn_scores_kernel<<<N, 256>>>(att_src, att_dst);

    // 5. segment max (stores leaky e)
    edge_max_kernel<<<(total * HEADS + 255) / 256, 256>>>(total);

    // 6. exp + segment sum
    edge_expsum_kernel<<<(total * HEADS + 255) / 256, 256>>>(total);

    // 7. gather-aggregate + residual + layernorm (fused)
    aggregate_ln_kernel<<<N, 256>>>(x, bias, ln_g, ln_b);

    // 8. FFN (mma.sync tensor path)
    gemm_ffn1_kernel<<<ggrid, 256>>>(W1, b1, N);
    gemm_ffn2_kernel<<<ggrid, 256>>>(W2, b2, out, N);
}

// round 16
// speedup vs baseline: 2.4535x; 1.0735x over previous
#include <cuda_runtime.h>
#include <cuda_bf16.h>
#include <math.h>
#include <stdint.h>

// ---------------------------------------------------------------------------
// Problem constants (fixed shapes per reference: N=50000, D=256, H=8, E=800000)
// ---------------------------------------------------------------------------
#define NMAX  50016
#define EMAX  800000
#define ENMAX (EMAX + NMAX)   // edges incl. self loops
#define DDIM  256
#define HEADS 8
#define HD    32
#define NBCHUNKS 256          // max scan chunks (ceil(50000/256)=196 <= 256)

// mma GEMM tiling
#define BK      32            // K per SMEM chunk
#define ASTRIDE 40            // bf16 elements per SMEM row (bank-conflict-free)

// ---------------------------------------------------------------------------
// Scratch (device globals -- no allocation allowed)
// ---------------------------------------------------------------------------
__device__ float g_xp [NMAX * DDIM];   // x @ W
__device__ float g_hn [NMAX * DDIM];   // layernorm output
__device__ float g_t1 [NMAX * DDIM];   // relu(hn@W1+b1)
__device__ float g_asrc[NMAX * HEADS];
__device__ float g_adst[NMAX * HEADS];
__device__ int   g_src32[ENMAX];
__device__ int   g_dst32[ENMAX];
__device__ int   g_deg   [NMAX];
__device__ int   g_rowptr[NMAX + 1];
__device__ int   g_cursor[NMAX];
__device__ int   g_eid   [ENMAX];
__device__ int   g_part  [NBCHUNKS];
__device__ int   g_is64;               // 1 if edge_index is int64, 0 if int32

// ---------------------------------------------------------------------------
// Helpers
// ---------------------------------------------------------------------------
__device__ __forceinline__ uint32_t pack_bf(__nv_bfloat16 a, __nv_bfloat16 b) {
    __nv_bfloat162 t;
    t.x = a; t.y = b;
    return *reinterpret_cast<uint32_t*>(&t);
}

// mma.sync m16n8k16 bf16 -> f32, accumulate in place (sm_80+, arch-portable)
__device__ __forceinline__ void mma_bf16(float* c, const uint32_t* a, const uint32_t* b) {
    asm volatile(
        "mma.sync.aligned.m16n8k16.row.col.f32.bf16.bf16.f32 "
        "{%0,%1,%2,%3}, {%4,%5,%6,%7}, {%8,%9}, {%0,%1,%2,%3};\n"
        : "+f"(c[0]), "+f"(c[1]), "+f"(c[2]), "+f"(c[3])
        : "r"(a[0]), "r"(a[1]), "r"(a[2]), "r"(a[3]), "r"(b[0]), "r"(b[1]));
}

// ---------------------------------------------------------------------------
// Tensor GEMM via mma.sync: C[M,256] = A[M,256] @ B[256,256] (+bias)(relu)
// 3-term bf16 hi/lo split. CTA = 128x128 tile, 256 threads (8 warps, 4m x 2n).
// If att_s != null, also computes per-row head dots with att_s/att_d
// (attention scores fused into the epilogue; acc is pre-bias).
// ---------------------------------------------------------------------------
__device__ void gemm_mma_body(const float* __restrict__ A, const float* __restrict__ B,
                              const float* __restrict__ bias, float* __restrict__ C,
                              int M, int relu,
                              const float* __restrict__ att_s,
                              const float* __restrict__ att_d)
{
    __shared__ __nv_bfloat16 Ah[128 * ASTRIDE];
    __shared__ __nv_bfloat16 Al[128 * ASTRIDE];
    __shared__ __nv_bfloat16 Bh[128 * ASTRIDE];
    __shared__ __nv_bfloat16 Bl[128 * ASTRIDE];

    const int tid  = threadIdx.x;
    const int wid  = tid >> 5;
    const int lane = tid & 31;
    const int wm   = wid & 3;       // 0..3 -> 32-row slice
    const int wn   = wid >> 2;      // 0..1 -> 64-col slice
    const int row0 = blockIdx.y * 128;
    const int col0 = blockIdx.x * 128;
    const int lr   = lane >> 2;     // 0..7
    const int lc   = lane & 3;      // 0..3

    float acc[2][8][4];
    #pragma unroll
    for (int mi = 0; mi < 2; mi++)
        #pragma unroll
        for (int ni = 0; ni < 8; ni++)
            #pragma unroll
            for (int q = 0; q < 4; q++) acc[mi][ni][q] = 0.0f;

    for (int kc = 0; kc < DDIM; kc += BK) {
        // ---- A chunk: 128 rows x 32 K fp32 -> hi/lo bf16 ----
        #pragma unroll
        for (int i = 0; i < 4; i++) {
            const int f4  = tid + i * 256;     // 1024 float4
            const int row = f4 >> 3;           // 8 f4 per row
            const int kq  = f4 & 7;            // 4 k each
            const int gr  = row0 + row;
            float4 v = make_float4(0.f, 0.f, 0.f, 0.f);
            if (gr < M) v = *reinterpret_cast<const float4*>(&A[gr * DDIM + kc + kq * 4]);
            __nv_bfloat16 hx = __float2bfloat16(v.x), hy = __float2bfloat16(v.y);
            __nv_bfloat16 hz = __float2bfloat16(v.z), hw = __float2bfloat16(v.w);
            __nv_bfloat16 lx = __float2bfloat16(v.x - __bfloat162float(hx));
            __nv_bfloat16 ly = __float2bfloat16(v.y - __bfloat162float(hy));
            __nv_bfloat16 lz = __float2bfloat16(v.z - __bfloat162float(hz));
            __nv_bfloat16 lw = __float2bfloat16(v.w - __bfloat162float(hw));
            const int o = row * ASTRIDE + kq * 4;
            *reinterpret_cast<uint32_t*>(&Ah[o])     = pack_bf(hx, hy);
            *reinterpret_cast<uint32_t*>(&Ah[o + 2]) = pack_bf(hz, hw);
            *reinterpret_cast<uint32_t*>(&Al[o])     = pack_bf(lx, ly);
            *reinterpret_cast<uint32_t*>(&Al[o + 2]) = pack_bf(lz, lw);
        }
        // ---- B chunk transposed: B[k][n] -> Bs[n][k] ----
        #pragma unroll
        for (int i = 0; i < 16; i++) {
            const int idx = tid + i * 256;     // 4096 elements
            const int k = idx >> 7;            // 0..31
            const int n = idx & 127;
            const float v = B[(kc + k) * DDIM + col0 + n];
            const __nv_bfloat16 h = __float2bfloat16(v);
            const __nv_bfloat16 l = __float2bfloat16(v - __bfloat162float(h));
            Bh[n * ASTRIDE + k] = h;
            Bl[n * ASTRIDE + k] = l;
        }
        __syncthreads();

        #pragma unroll
        for (int ks = 0; ks < 2; ks++) {       // two k16 steps
            const int pb = ks * 8;             // k-pair base (u32 pairs)
            uint32_t ah[2][4], al[2][4];
            #pragma unroll
            for (int mi = 0; mi < 2; mi++) {
                const int r  = wm * 32 + mi * 16 + lr;
                const int o0 = r * ASTRIDE + (pb + lc) * 2;
                const int o8 = (r + 8) * ASTRIDE + (pb + lc) * 2;
                ah[mi][0] = *reinterpret_cast<uint32_t*>(&Ah[o0]);
                ah[mi][1] = *reinterpret_cast<uint32_t*>(&Ah[o8]);
                ah[mi][2] = *reinterpret_cast<uint32_t*>(&Ah[o0 + 8]);
                ah[mi][3] = *reinterpret_cast<uint32_t*>(&Ah[o8 + 8]);
                al[mi][0] = *reinterpret_cast<uint32_t*>(&Al[o0]);
                al[mi][1] = *reinterpret_cast<uint32_t*>(&Al[o8]);
                al[mi][2] = *reinterpret_cast<uint32_t*>(&Al[o0 + 8]);
                al[mi][3] = *reinterpret_cast<uint32_t*>(&Al[o8 + 8]);
            }
            uint32_t bh[8][2], bl[8][2];
            #pragma unroll
            for (int ni = 0; ni < 8; ni++) {
                const int n = wn * 64 + ni * 8 + lr;
                const int o = n * ASTRIDE + (pb + lc) * 2;
                bh[ni][0] = *reinterpret_cast<uint32_t*>(&Bh[o]);
                bh[ni][1] = *reinterpret_cast<uint32_t*>(&Bh[o + 8]);
                bl[ni][0] = *reinterpret_cast<uint32_t*>(&Bl[o]);
                bl[ni][1] = *reinterpret_cast<uint32_t*>(&Bl[o + 8]);
            }
            #pragma unroll
            for (int mi = 0; mi < 2; mi++)
                #pragma unroll
                for (int ni = 0; ni < 8; ni++) {
                    mma_bf16(acc[mi][ni], ah[mi], bh[ni]);
                    mma_bf16(acc[mi][ni], ah[mi], bl[ni]);
                    mma_bf16(acc[mi][ni], al[mi], bh[ni]);
                }
        }
        __syncthreads();
    }

    // ---- store epilogue (bias / relu) ----
    #pragma unroll
    for (int mi = 0; mi < 2; mi++) {
        #pragma unroll
        for (int half = 0; half < 2; half++) {
            const int r = row0 + wm * 32 + mi * 16 + lr + half * 8;
            if (r < M) {
                #pragma unroll
                for (int ni = 0; ni < 8; ni++) {
                    const int c = col0 + wn * 64 + ni * 8 + lc * 2;
                    float2 o;
                    o.x = acc[mi][ni][half * 2 + 0];
                    o.y = acc[mi][ni][half * 2 + 1];
                    if (bias) {
                        o.x += bias[c];
                        o.y += bias[c + 1];
                    }
                    if (relu) {
                        o.x = fmaxf(o.x, 0.f);
                        o.y = fmaxf(o.y, 0.f);
                    }
                    *reinterpret_cast<float2*>(&C[r * DDIM + c]) = o;
                }
            }
        }
    }

    // ---- fused attention scores (xW GEMM only) ----
    // Warp's 64 cols = heads hA = 4*blockIdx.x + 2*wn and hA+1 (32 cols each).
    // Per row: dot(acc_row_slice, att) reduced across the 4 lc lanes.
    if (att_s) {
        #pragma unroll
        for (int mi = 0; mi < 2; mi++) {
            #pragma unroll
            for (int half = 0; half < 2; half++) {
                const int r = row0 + wm * 32 + mi * 16 + lr + half * 8;
                float sA = 0.f, sB = 0.f, dA = 0.f, dB = 0.f;
                #pragma unroll
                for (int ni = 0; ni < 8; ni++) {
                    const int c = col0 + wn * 64 + ni * 8 + lc * 2;
                    const float a0 = acc[mi][ni][half * 2 + 0];
                    const float a1 = acc[mi][ni][half * 2 + 1];
                    const float ps = a0 * att_s[c] + a1 * att_s[c + 1];
                    const float pd = a0 * att_d[c] + a1 * att_d[c + 1];
                    if (ni < 4) { sA += ps; dA += pd; }
                    else        { sB += ps; dB += pd; }
                }
                // reduce across lc (lane bits 0-1)
                sA += __shfl_xor_sync(0xffffffffu, sA, 1);
                sA += __shfl_xor_sync(0xffffffffu, sA, 2);
                sB += __shfl_xor_sync(0xffffffffu, sB, 1);
                sB += __shfl_xor_sync(0xffffffffu, sB, 2);
                dA += __shfl_xor_sync(0xffffffffu, dA, 1);
                dA += __shfl_xor_sync(0xffffffffu, dA, 2);
                dB += __shfl_xor_sync(0xffffffffu, dB, 1);
                dB += __shfl_xor_sync(0xffffffffu, dB, 2);
                if (lc == 0 && r < M) {
                    const int hA = 4 * blockIdx.x + 2 * wn;
                    g_asrc[r * HEADS + hA]     = sA;
                    g_asrc[r * HEADS + hA + 1] = sB;
                    g_adst[r * HEADS + hA]     = dA;
                    g_adst[r * HEADS + hA + 1] = dB;
                }
            }
        }
    }
}

__global__ __launch_bounds__(256) void gemm_xW_kernel(
    const float* __restrict__ x, const float* __restrict__ W,
    const float* __restrict__ att_s, const float* __restrict__ att_d, int M)
{
    gemm_mma_body(x, W, nullptr, g_xp, M, 0, att_s, att_d);
}

__global__ __launch_bounds__(256) void gemm_ffn1_kernel(
    const float* __restrict__ W1, const float* __restrict__ b1, int M)
{
    gemm_mma_body(g_hn, W1, b1, g_t1, M, 1, nullptr, nullptr);
}

__global__ __launch_bounds__(256) void gemm_ffn2_kernel(
    const float* __restrict__ W2, const float* __restrict__ b2,
    float* __restrict__ out, int M)
{
    gemm_mma_body(g_t1, W2, b2, out, M, 0, nullptr, nullptr);
}

// ---------------------------------------------------------------------------
// Dtype detection: int64 little-endian with values < 2^31 -> odd words all 0.
// ---------------------------------------------------------------------------
__global__ void detect_dtype_kernel(const int* ei32, int E) {
    if (threadIdx.x == 0 && blockIdx.x == 0) {
        int cnt = (E < 128) ? E : 128;
        int is64 = 1;
        for (int i = 0; i < cnt; i++) {
            if (ei32[2 * i + 1] != 0) { is64 = 0; break; }
        }
        g_is64 = is64;
    }
}

// ---------------------------------------------------------------------------
// Init: deg=0
// ---------------------------------------------------------------------------
__global__ void init_kernel(int n) {
    int idx = blockIdx.x * blockDim.x + threadIdx.x;
    if (idx < n) g_deg[idx] = 0;
}

// ---------------------------------------------------------------------------
// Convert edge indices to int32, count in-degree (self-loops appended E..E+N-1)
// ---------------------------------------------------------------------------
__global__ void deg_convert_kernel(const void* __restrict__ ei, int E, int n) {
    const int e = blockIdx.x * blockDim.x + threadIdx.x;
    const int total = E + n;
    if (e >= total) return;
    int src, dst;
    if (e < E) {
        if (g_is64) {
            const long long* p = (const long long*)ei;
            src = (int)p[e]; dst = (int)p[E + e];
        } else {
            const int* p = (const int*)ei;
            src = p[e]; dst = p[E + e];
        }
        if ((unsigned)src >= (unsigned)n) src = 0;
        if ((unsigned)dst >= (unsigned)n) dst = 0;
    } else {
        src = dst = e - E;
    }
    g_src32[e] = src;
    g_dst32[e] = dst;
    atomicAdd(&g_deg[dst], 1);
}

// ---------------------------------------------------------------------------
// Two-level exclusive scan of g_deg -> g_rowptr
// ---------------------------------------------------------------------------
__global__ void scan_chunk_kernel(int n) {
    __shared__ int s[256];
    const int tid = threadIdx.x;
    const int i = blockIdx.x * 256 + tid;
    int v = (i < n) ? g_deg[i] : 0;
    s[tid] = v;
    __syncthreads();
    #pragma unroll
    for (int o = 1; o < 256; o <<= 1) {
        int t = (tid >= o) ? s[tid - o] : 0;
        __syncthreads();
        s[tid] += t;
        __syncthreads();
    }
    if (i < n) g_rowptr[i] = s[tid] - v;
    if (tid == 255) g_part[blockIdx.x] = s[255];
}

__global__ void scan_part_kernel(int nb) {
    __shared__ int s[256];
    const int tid = threadIdx.x;
    int v = (tid < nb) ? g_part[tid] : 0;
    s[tid] = v;
    __syncthreads();
    #pragma unroll
    for (int o = 1; o < 256; o <<= 1) {
        int t = (tid >= o) ? s[tid - o] : 0;
        __syncthreads();
        s[tid] += t;
        __syncthreads();
    }
    if (tid < nb) g_part[tid] = s[tid] - v;
}

__global__ void scan_add_kernel(int n, int total) {
    const int i = blockIdx.x * 256 + threadIdx.x;
    if (i < n) {
        int r = g_rowptr[i] + g_part[blockIdx.x];
        g_rowptr[i] = r;
        g_cursor[i] = r;
    }
    if (i == 0) g_rowptr[n] = total;
}

__global__ void csr_fill_kernel(int total) {
    const int e = blockIdx.x * blockDim.x + threadIdx.x;
    if (e >= total) return;
    const int dst = g_dst32[e];
    const int pos = atomicAdd(&g_cursor[dst], 1);
    g_eid[pos] = e;
}

// ---------------------------------------------------------------------------
// Fused segment-softmax + gather-aggregation + residual + LayerNorm.
// One block per dst node; warp = head; lane = dim within head.
// Pass A: lane-strided max of leaky(e) per head (g_asrc is L2-resident).
// Pass B: acc = sum ex * xp[src,:], den = sum ex; result acc/(den+eps).
// ---------------------------------------------------------------------------
__global__ __launch_bounds__(256) void aggregate_ln_kernel(
    const float* __restrict__ x,
    const float* __restrict__ bias,
    const float* __restrict__ gamma,
    const float* __restrict__ beta)
{
    const int node = blockIdx.x;
    const int tid = threadIdx.x;
    const int h = tid >> 5;
    const int lane = tid & 31;
    const int beg = g_rowptr[node];
    const int end = g_rowptr[node + 1];
    const float adst = g_adst[node * HEADS + h];

    // ---- pass A: warp max of leaky(e) ----
    float mx = -1e30f;
    for (int i = beg + lane; i < end; i += 32) {
        const int e = g_eid[i];
        const int s = g_src32[e];
        float v = g_asrc[s * HEADS + h] + adst;
        v = (v > 0.0f) ? v : 0.2f * v;
        mx = fmaxf(mx, v);
    }
    #pragma unroll
    for (int o = 16; o > 0; o >>= 1)
        mx = fmaxf(mx, __shfl_xor_sync(0xffffffffu, mx, o));

    // ---- pass B: accumulate ex*xp and den ----
    float acc = 0.0f, den = 0.0f;
    int i = beg;
    for (; i + 2 <= end; i += 2) {
        const int e0 = g_eid[i], e1 = g_eid[i + 1];
        const int s0 = g_src32[e0], s1 = g_src32[e1];
        float v0 = g_asrc[s0 * HEADS + h] + adst;
        float v1 = g_asrc[s1 * HEADS + h] + adst;
        v0 = (v0 > 0.0f) ? v0 : 0.2f * v0;
        v1 = (v1 > 0.0f) ? v1 : 0.2f * v1;
        const float ex0 = __expf(v0 - mx);
        const float ex1 = __expf(v1 - mx);
        const float p0 = g_xp[s0 * DDIM + tid];
        const float p1 = g_xp[s1 * DDIM + tid];
        den += ex0 + ex1;
        acc += ex0 * p0 + ex1 * p1;
    }
    for (; i < end; i++) {
        const int e = g_eid[i];
        const int s = g_src32[e];
        float v = g_asrc[s * HEADS + h] + adst;
        v = (v > 0.0f) ? v : 0.2f * v;
        const float ex = __expf(v - mx);
        den += ex;
        acc += ex * g_xp[s * DDIM + tid];
    }
    acc = acc / (den + 1e-16f);

    // ---- residual + LayerNorm ----
    __shared__ float ws[8], ws2[8];
    float r = acc + bias[tid] + x[node * DDIM + tid];
    float sm = r, s2 = r * r;
    #pragma unroll
    for (int o = 16; o > 0; o >>= 1) {
        sm += __shfl_down_sync(0xffffffffu, sm, o);
        s2 += __shfl_down_sync(0xffffffffu, s2, o);
    }
    if (lane == 0) { ws[h] = sm; ws2[h] = s2; }
    __syncthreads();
    if (tid == 0) {
        float a = 0.f, b = 0.f;
        #pragma unroll
        for (int k = 0; k < 8; k++) { a += ws[k]; b += ws2[k]; }
        ws[0] = a; ws2[0] = b;
    }
    __syncthreads();
    const float mean = ws[0] * (1.0f / DDIM);
    const float var = ws2[0] * (1.0f / DDIM) - mean * mean;
    const float inv = rsqrtf(var + 1e-5f);
    g_hn[node * DDIM + tid] = (r - mean) * inv * gamma[tid] + beta[tid];
}

// ---------------------------------------------------------------------------
// Launch
// ---------------------------------------------------------------------------
extern "C" void kernel_launch(void* const* d_in, const int* in_sizes, int n_in,
                              void* d_out, int out_size)
{
    const float* x        = (const float*)d_in[0];
    const void*  ei       = d_in[1];
    // d_in[2] = edge_attr (unused)
    const float* W        = (const float*)d_in[3];
    const float* att_src  = (const float*)d_in[4];
    const float* att_dst  = (const float*)d_in[5];
    const float* bias     = (const float*)d_in[6];
    const float* ln_g     = (const float*)d_in[7];
    const float* ln_b     = (const float*)d_in[8];
    const float* W1       = (const float*)d_in[9];
    const float* b1       = (const float*)d_in[10];
    const float* W2       = (const float*)d_in[11];
    const float* b2       = (const float*)d_in[12];
    float*       out      = (float*)d_out;

    const int N = in_sizes[0] / DDIM;
    const int E = in_sizes[1] / 2;
    const int total = E + N;
    const int nchunks = (N + 255) / 256;
    const dim3 ggrid(DDIM / 128, (N + 127) / 128);

    // 0. detect dtype, zero degree counters
    detect_dtype_kernel<<<1, 32>>>((const int*)ei, E);
    init_kernel<<<(N + 255) / 256, 256>>>(N);

    // 1. convert indices + degree count
    deg_convert_kernel<<<(total + 255) / 256, 256>>>(ei, E, N);

    // 2. CSR build (exclusive scan + fill)
    scan_chunk_kernel<<<nchunks, 256>>>(N);
    scan_part_kernel<<<1, 256>>>(nchunks);
    scan_add_kernel<<<nchunks, 256>>>(N, total);
    csr_fill_kernel<<<(total + 255) / 256, 256>>>(total);

    // 3. xp = x @ W with fused attention scores (mma.sync tensor path)
    gemm_xW_kernel<<<ggrid, 256>>>(x, W, att_src, att_dst, N);

    // 4. fused segment-softmax + aggregate + residual + layernorm
    aggregate_ln_kernel<<<N, 256>>>(x, bias, ln_g, ln_b);

    // 5. FFN (mma.sync tensor path)
    gemm_ffn1_kernel<<<ggrid, 256>>>(W1, b1, N);
    gemm_ffn2_kernel<<<ggrid, 256>>>(W2, b2, out, N);
}